// round 4
// baseline (speedup 1.0000x reference)
#include <cuda_runtime.h>
#include <math.h>

#define BB   16
#define SS   1024
#define EE   256
#define HH   256
#define G4   1024
#define WT_  256

// ---------- static scratch ----------
__device__ float g_Af[(size_t)BB * SS * G4];
__device__ float g_Ab[(size_t)BB * SS * G4];
__device__ float g_G [(size_t)BB * SS * G4];
__device__ float g_hn[(size_t)BB * SS * HH];
__device__ float g_hb[(size_t)BB * SS * HH];
__device__ float g_P [(size_t)BB * SS * WT_];
__device__ float g_b3[(size_t)BB * SS * WT_];
__device__ float g_WTf[G4 * HH];
__device__ float g_WTb[G4 * HH];
__device__ float g_WTd[G4 * HH];

// ---------- helpers ----------
__device__ __forceinline__ unsigned long long fma2(unsigned long long a,
                                                   unsigned long long b,
                                                   unsigned long long c) {
    unsigned long long d;
    asm("fma.rn.f32x2 %0, %1, %2, %3;" : "=l"(d) : "l"(a), "l"(b), "l"(c));
    return d;
}
__device__ __forceinline__ unsigned long long splat2(float a) {
    unsigned long long d; unsigned int u = __float_as_uint(a);
    asm("mov.b64 %0, {%1, %1};" : "=l"(d) : "r"(u));
    return d;
}
__device__ __forceinline__ float2 unpk(unsigned long long v) {
    float2 r;
    asm("mov.b64 {%0, %1}, %2;" : "=f"(r.x), "=f"(r.y) : "l"(v));
    return r;
}
__device__ __forceinline__ float sigf(float x) { return 1.0f / (1.0f + expf(-x)); }

// ---------- transpose [256,1024] -> [1024,256] ----------
__global__ void transpose_w(const float* __restrict__ in, float* __restrict__ out) {
    __shared__ float tile[32][33];
    int x = blockIdx.x * 32 + threadIdx.x;
    int y = blockIdx.y * 32 + threadIdx.y;
    tile[threadIdx.y][threadIdx.x] = in[y * G4 + x];
    __syncthreads();
    int ox = blockIdx.y * 32 + threadIdx.x;
    int oy = blockIdx.x * 32 + threadIdx.y;
    out[oy * HH + ox] = tile[threadIdx.x][threadIdx.y];
}

// ---------- SGEMM: C[M,N] (+)= A[M,K]@B[K,N], row-major, M%128==0, N%128==0, K%16==0 ----------
__global__ __launch_bounds__(256, 2)
void sgemm128(const float* __restrict__ A, const float* __restrict__ B,
              float* __restrict__ C, int M, int N, int K, int accum) {
    __shared__ __align__(16) float As[16][128];
    __shared__ __align__(16) float Bs[16][128];
    int tid = threadIdx.x;
    int m0 = blockIdx.y * 128, n0 = blockIdx.x * 128;
    int tr = tid >> 4, tc = tid & 15;
    int rowA = m0 + tr * 8, colB = n0 + tc * 8;

    unsigned long long acc[8][4];
#pragma unroll
    for (int i = 0; i < 8; i++)
#pragma unroll
        for (int p = 0; p < 4; p++) acc[i][p] = 0ull;

    for (int k0 = 0; k0 < K; k0 += 16) {
#pragma unroll
        for (int l = 0; l < 2; l++) {
            int i = tid + l * 256;
            int r = i >> 2, c = (i & 3) * 4;
            float4 a4 = *(const float4*)(A + (size_t)(m0 + r) * K + k0 + c);
            As[c + 0][r] = a4.x; As[c + 1][r] = a4.y;
            As[c + 2][r] = a4.z; As[c + 3][r] = a4.w;
            int rb = i >> 5, cb = (i & 31) * 4;
            *(float4*)&Bs[rb][cb] = *(const float4*)(B + (size_t)(k0 + rb) * N + n0 + cb);
        }
        __syncthreads();
#pragma unroll
        for (int kk = 0; kk < 16; kk++) {
            float4 a0 = *(const float4*)&As[kk][tr * 8];
            float4 a1 = *(const float4*)&As[kk][tr * 8 + 4];
            ulonglong2 b0 = *(const ulonglong2*)&Bs[kk][tc * 8];
            ulonglong2 b1 = *(const ulonglong2*)&Bs[kk][tc * 8 + 4];
            float av[8] = {a0.x, a0.y, a0.z, a0.w, a1.x, a1.y, a1.z, a1.w};
#pragma unroll
            for (int i = 0; i < 8; i++) {
                unsigned long long s = splat2(av[i]);
                acc[i][0] = fma2(s, b0.x, acc[i][0]);
                acc[i][1] = fma2(s, b0.y, acc[i][1]);
                acc[i][2] = fma2(s, b1.x, acc[i][2]);
                acc[i][3] = fma2(s, b1.y, acc[i][3]);
            }
        }
        __syncthreads();
    }
#pragma unroll
    for (int i = 0; i < 8; i++) {
        float* cp = C + (size_t)(rowA + i) * N + colB;
#pragma unroll
        for (int p = 0; p < 4; p++) {
            float2 v = unpk(acc[i][p]);
            if (accum) { v.x += cp[2 * p]; v.y += cp[2 * p + 1]; }
            cp[2 * p] = v.x; cp[2 * p + 1] = v.y;
        }
    }
}

// ---------- encoder: 16 CTAs = (dir, batch-pair), 1024 threads ----------
__global__ __launch_bounds__(1024)
void lstm_encoder(const float* __restrict__ Af, const float* __restrict__ Ab,
                  const float* __restrict__ WTf, const float* __restrict__ WTb,
                  const float* __restrict__ bf, const float* __restrict__ bbp,
                  float* __restrict__ hn, float* __restrict__ hb) {
    int d = blockIdx.x >> 3, g = blockIdx.x & 7;
    const float* A    = d ? Ab  : Af;
    const float* WT   = d ? WTb : WTf;
    const float* bias = d ? bbp : bf;
    float* H          = d ? hb  : hn;
    int b0 = 2 * g, b1 = 2 * g + 1;

    __shared__ __align__(16) float hs[2][HH];
    __shared__ float zs[2][G4];
    int j = threadIdx.x;
    if (j < HH) { hs[0][j] = 0.f; hs[1][j] = 0.f; }
    float bj = bias[j];
    float c = 0.f;
    const ulonglong2* wrow = (const ulonglong2*)(WT + (size_t)j * HH);
    __syncthreads();

    for (int step = 0; step < SS; ++step) {
        int t = d ? (SS - 1 - step) : step;
        unsigned long long a0 = 0ull, a1 = 0ull;
        const ulonglong2* h0p = (const ulonglong2*)hs[0];
        const ulonglong2* h1p = (const ulonglong2*)hs[1];
#pragma unroll 8
        for (int k = 0; k < 64; ++k) {
            ulonglong2 w  = wrow[k];
            ulonglong2 x0 = h0p[k], x1 = h1p[k];
            a0 = fma2(x0.x, w.x, a0); a0 = fma2(x0.y, w.y, a0);
            a1 = fma2(x1.x, w.x, a1); a1 = fma2(x1.y, w.y, a1);
        }
        float2 u0 = unpk(a0), u1 = unpk(a1);
        zs[0][j] = A[(size_t)(b0 * SS + t) * G4 + j] + bj + u0.x + u0.y;
        zs[1][j] = A[(size_t)(b1 * SS + t) * G4 + j] + bj + u1.x + u1.y;
        __syncthreads();
        if (j < 512) {
            int bi = j >> 8, k = j & 255;
            const float* z = zs[bi];
            float iv = sigf(z[k]);
            float fv = sigf(z[HH + k]);
            float gv = tanhf(z[2 * HH + k]);
            float ov = sigf(z[3 * HH + k]);
            c = fv * c + iv * gv;
            float h = ov * tanhf(c);
            hs[bi][k] = h;
            H[(size_t)((bi ? b1 : b0) * SS + t) * HH + k] = h;
        }
        __syncthreads();
    }
}

// ---------- decoder: 16 CTAs (one batch each), 1024 threads ----------
__global__ __launch_bounds__(1024)
void lstm_decoder(const float* __restrict__ G, const float* __restrict__ WT,
                  const float* __restrict__ bias, const float* __restrict__ hn,
                  const float* __restrict__ P, const float* __restrict__ b3,
                  const float* __restrict__ W4, const float* __restrict__ vt1,
                  float* __restrict__ out) {
    int b = blockIdx.x, j = threadIdx.x;
    __shared__ __align__(16) float hs[HH];
    __shared__ __align__(16) float qv[WT_];
    __shared__ __align__(16) float vs[WT_];
    __shared__ float zs[G4];
    __shared__ float rs[SS];
    __shared__ int   ri[SS];
    __shared__ int   bond_s;

    float c = 0.f;
    if (j < HH) {
        hs[j] = 0.f;
        c = hn[(size_t)(b * SS + SS - 1) * HH + j];   // cell init = fwd enc hn[-1]
        vs[j] = vt1[j];
    }
    out[(size_t)j * BB + b] = 0.f;                    // zero this batch's output column
    if (j == 0) bond_s = 0;
    float bj = bias[j];
    const ulonglong2* wrow = (const ulonglong2*)(WT + (size_t)j * HH);
    __syncthreads();

    for (int t = 0; t < SS; ++t) {
        unsigned long long a0 = 0ull;
        const ulonglong2* hp = (const ulonglong2*)hs;
#pragma unroll 8
        for (int k = 0; k < 64; ++k) {
            ulonglong2 w = wrow[k];
            ulonglong2 h2 = hp[k];
            a0 = fma2(h2.x, w.x, a0);
            a0 = fma2(h2.y, w.y, a0);
        }
        float2 u = unpk(a0);
        float z = bj + u.x + u.y;
        if (t > 0) z += G[(size_t)(b * SS + t - 1) * G4 + j];
        zs[j] = z;
        __syncthreads();
        if (j < HH) {
            float iv = sigf(zs[j]);
            float fv = sigf(zs[HH + j]);
            float gv = tanhf(zs[2 * HH + j]);
            float ov = sigf(zs[3 * HH + j]);
            c = fv * c + iv * gv;
            hs[j] = ov * tanhf(c);
        }
        __syncthreads();

        if (t == bond_s) {   // decision step: pointer attention + argmax
            if (j < WT_) {
                float acc = b3[(size_t)(b * SS + t) * WT_ + j];
                for (int k = 0; k < HH; ++k) acc += hs[k] * W4[(size_t)k * WT_ + j];
                qv[j] = acc;
            }
            __syncthreads();
            int pos = t + j;
            float sc = -3.4e38f;
            if (pos < SS) {
                const float4* Pr = (const float4*)(P + (size_t)(b * SS + pos) * WT_);
                const float4* Q  = (const float4*)qv;
                const float4* V  = (const float4*)vs;
                float s = 0.f;
                for (int k = 0; k < 64; ++k) {
                    float4 p = Pr[k], q4 = Q[k], v4 = V[k];
                    s += v4.x * tanhf(p.x + q4.x);
                    s += v4.y * tanhf(p.y + q4.y);
                    s += v4.z * tanhf(p.z + q4.z);
                    s += v4.w * tanhf(p.w + q4.w);
                }
                sc = s;
            }
            rs[j] = sc; ri[j] = pos;
            __syncthreads();
            for (int off = 512; off > 0; off >>= 1) {
                if (j < off) {
                    float so = rs[j + off]; int io = ri[j + off];
                    if (so > rs[j] || (so == rs[j] && io < ri[j])) { rs[j] = so; ri[j] = io; }
                }
                __syncthreads();
            }
            if (j == 0) {
                out[(size_t)ri[0] * BB + b] = 1.0f;
                bond_s = ri[0];
            }
            __syncthreads();
        }
    }
}

extern "C" void kernel_launch(void* const* d_in, const int* in_sizes, int n_in,
                              void* d_out, int out_size) {
    const float* x        = (const float*)d_in[0];
    const float* eWih_f   = (const float*)d_in[1];
    const float* eWhh_f   = (const float*)d_in[2];
    const float* eb_f     = (const float*)d_in[3];
    const float* eWih_b   = (const float*)d_in[4];
    const float* eWhh_b   = (const float*)d_in[5];
    const float* eb_b     = (const float*)d_in[6];
    const float* dWih     = (const float*)d_in[7];
    const float* dWhh     = (const float*)d_in[8];
    const float* db       = (const float*)d_in[9];
    const float* W1       = (const float*)d_in[10];
    const float* W2       = (const float*)d_in[11];
    const float* W3       = (const float*)d_in[12];
    const float* W4       = (const float*)d_in[13];
    const float* vt1      = (const float*)d_in[14];
    float* out = (float*)d_out;

    float *Af, *Ab, *G, *hn, *hb, *P, *b3, *WTf, *WTb, *WTd;
    cudaGetSymbolAddress((void**)&Af,  g_Af);
    cudaGetSymbolAddress((void**)&Ab,  g_Ab);
    cudaGetSymbolAddress((void**)&G,   g_G);
    cudaGetSymbolAddress((void**)&hn,  g_hn);
    cudaGetSymbolAddress((void**)&hb,  g_hb);
    cudaGetSymbolAddress((void**)&P,   g_P);
    cudaGetSymbolAddress((void**)&b3,  g_b3);
    cudaGetSymbolAddress((void**)&WTf, g_WTf);
    cudaGetSymbolAddress((void**)&WTb, g_WTb);
    cudaGetSymbolAddress((void**)&WTd, g_WTd);

    dim3 tb(32, 32), tg(G4 / 32, HH / 32);
    transpose_w<<<tg, tb>>>(eWhh_f, WTf);
    transpose_w<<<tg, tb>>>(eWhh_b, WTb);
    transpose_w<<<tg, tb>>>(dWhh,   WTd);

    const int M = BB * SS;
    // encoder input projections
    sgemm128<<<dim3(G4 / 128, M / 128), 256>>>(x, eWih_f, Af, M, G4, EE, 0);
    sgemm128<<<dim3(G4 / 128, M / 128), 256>>>(x, eWih_b, Ab, M, G4, EE, 0);

    lstm_encoder<<<16, 1024>>>(Af, Ab, WTf, WTb, eb_f, eb_b, hn, hb);

    // decoder input projection: G = x @ dWih[:E] + hn @ dWih[E:]
    sgemm128<<<dim3(G4 / 128, M / 128), 256>>>(x,  dWih,            G, M, G4, EE, 0);
    sgemm128<<<dim3(G4 / 128, M / 128), 256>>>(hn, dWih + EE * G4,  G, M, G4, HH, 1);

    // P = hn @ W1[:H] + hb @ W1[H:] + x @ W2 ; b3 = x @ W3
    sgemm128<<<dim3(WT_ / 128, M / 128), 256>>>(hn, W1,            P, M, WT_, HH, 0);
    sgemm128<<<dim3(WT_ / 128, M / 128), 256>>>(hb, W1 + HH * WT_, P, M, WT_, HH, 1);
    sgemm128<<<dim3(WT_ / 128, M / 128), 256>>>(x,  W2,            P, M, WT_, EE, 1);
    sgemm128<<<dim3(WT_ / 128, M / 128), 256>>>(x,  W3,            b3, M, WT_, EE, 0);

    lstm_decoder<<<16, 1024>>>(G, WTd, db, hn, P, b3, W4, vt1, out);
}

// round 5
// speedup vs baseline: 12.0156x; 12.0156x over previous
#include <cuda_runtime.h>
#include <math.h>

#define BB   16
#define SS   1024
#define EE   256
#define HH   256
#define G4   1024
#define WT_  256

// ---------- static scratch ----------
__device__ float g_Af[(size_t)BB * SS * G4];
__device__ float g_Ab[(size_t)BB * SS * G4];
__device__ float g_G [(size_t)BB * SS * G4];
__device__ float g_hn[(size_t)BB * SS * HH];
__device__ float g_hb[(size_t)BB * SS * HH];
__device__ float g_P [(size_t)BB * SS * WT_];
__device__ float g_b3[(size_t)BB * SS * WT_];
__device__ float g_WTf[G4 * HH];
__device__ float g_WTb[G4 * HH];
__device__ float g_WTd[G4 * HH];

// ---------- helpers ----------
__device__ __forceinline__ unsigned long long fma2(unsigned long long a,
                                                   unsigned long long b,
                                                   unsigned long long c) {
    unsigned long long d;
    asm("fma.rn.f32x2 %0, %1, %2, %3;" : "=l"(d) : "l"(a), "l"(b), "l"(c));
    return d;
}
__device__ __forceinline__ unsigned long long splat2(float a) {
    unsigned long long d; unsigned int u = __float_as_uint(a);
    asm("mov.b64 %0, {%1, %1};" : "=l"(d) : "r"(u));
    return d;
}
__device__ __forceinline__ float2 unpk(unsigned long long v) {
    float2 r;
    asm("mov.b64 {%0, %1}, %2;" : "=f"(r.x), "=f"(r.y) : "l"(v));
    return r;
}
__device__ __forceinline__ float sigf(float x) { return 1.0f / (1.0f + expf(-x)); }

__device__ __forceinline__ unsigned int smem_u32(const void* p) {
    unsigned int a;
    asm("{ .reg .u64 t; cvta.to.shared.u64 t, %1; cvt.u32.u64 %0, t; }" : "=r"(a) : "l"(p));
    return a;
}
__device__ __forceinline__ void st_cluster_f32(unsigned int addr, unsigned int rank, float v) {
    unsigned int ra;
    asm volatile("mapa.shared::cluster.u32 %0, %1, %2;" : "=r"(ra) : "r"(addr), "r"(rank));
    asm volatile("st.shared::cluster.f32 [%0], %1;" :: "r"(ra), "f"(v) : "memory");
}
__device__ __forceinline__ void cluster_sync() {
    asm volatile("barrier.cluster.arrive.aligned;" ::: "memory");
    asm volatile("barrier.cluster.wait.aligned;"   ::: "memory");
}

// ---------- transpose [256,1024] -> [1024,256] ----------
__global__ void transpose_w(const float* __restrict__ in, float* __restrict__ out) {
    __shared__ float tile[32][33];
    int x = blockIdx.x * 32 + threadIdx.x;
    int y = blockIdx.y * 32 + threadIdx.y;
    tile[threadIdx.y][threadIdx.x] = in[y * G4 + x];
    __syncthreads();
    int ox = blockIdx.y * 32 + threadIdx.x;
    int oy = blockIdx.x * 32 + threadIdx.y;
    out[oy * HH + ox] = tile[threadIdx.x][threadIdx.y];
}

// ---------- SGEMM (unchanged, proven) ----------
__global__ __launch_bounds__(256, 2)
void sgemm128(const float* __restrict__ A, const float* __restrict__ B,
              float* __restrict__ C, int M, int N, int K, int accum) {
    __shared__ __align__(16) float As[16][128];
    __shared__ __align__(16) float Bs[16][128];
    int tid = threadIdx.x;
    int m0 = blockIdx.y * 128, n0 = blockIdx.x * 128;
    int tr = tid >> 4, tc = tid & 15;
    int rowA = m0 + tr * 8, colB = n0 + tc * 8;

    unsigned long long acc[8][4];
#pragma unroll
    for (int i = 0; i < 8; i++)
#pragma unroll
        for (int p = 0; p < 4; p++) acc[i][p] = 0ull;

    for (int k0 = 0; k0 < K; k0 += 16) {
#pragma unroll
        for (int l = 0; l < 2; l++) {
            int i = tid + l * 256;
            int r = i >> 2, c = (i & 3) * 4;
            float4 a4 = *(const float4*)(A + (size_t)(m0 + r) * K + k0 + c);
            As[c + 0][r] = a4.x; As[c + 1][r] = a4.y;
            As[c + 2][r] = a4.z; As[c + 3][r] = a4.w;
            int rb = i >> 5, cb = (i & 31) * 4;
            *(float4*)&Bs[rb][cb] = *(const float4*)(B + (size_t)(k0 + rb) * N + n0 + cb);
        }
        __syncthreads();
#pragma unroll
        for (int kk = 0; kk < 16; kk++) {
            float4 a0 = *(const float4*)&As[kk][tr * 8];
            float4 a1 = *(const float4*)&As[kk][tr * 8 + 4];
            ulonglong2 b0 = *(const ulonglong2*)&Bs[kk][tc * 8];
            ulonglong2 b1 = *(const ulonglong2*)&Bs[kk][tc * 8 + 4];
            float av[8] = {a0.x, a0.y, a0.z, a0.w, a1.x, a1.y, a1.z, a1.w};
#pragma unroll
            for (int i = 0; i < 8; i++) {
                unsigned long long s = splat2(av[i]);
                acc[i][0] = fma2(s, b0.x, acc[i][0]);
                acc[i][1] = fma2(s, b0.y, acc[i][1]);
                acc[i][2] = fma2(s, b1.x, acc[i][2]);
                acc[i][3] = fma2(s, b1.y, acc[i][3]);
            }
        }
        __syncthreads();
    }
#pragma unroll
    for (int i = 0; i < 8; i++) {
        float* cp = C + (size_t)(rowA + i) * N + colB;
#pragma unroll
        for (int p = 0; p < 4; p++) {
            float2 v = unpk(acc[i][p]);
            if (accum) { v.x += cp[2 * p]; v.y += cp[2 * p + 1]; }
            cp[2 * p] = v.x; cp[2 * p + 1] = v.y;
        }
    }
}

// ======================================================================
// Weight-stationary cluster LSTM. Cluster of 8 CTAs, 512 threads each.
// CTA rank r owns h-indices [32r, 32r+32) -> 128 gate rows; each thread
// holds a quarter-row (64 weights) in registers. h (256 floats/batch)
// replicated in every CTA's smem, double-buffered, DSMEM-broadcast.
// Two batches per cluster amortize the weight registers.
// ======================================================================

// ---------- encoder: 16 clusters (dir x batch-pair) = 128 CTAs ----------
__global__ __launch_bounds__(512, 1) __cluster_dims__(8, 1, 1)
void lstm_enc(const float* __restrict__ Af, const float* __restrict__ Ab,
              const float* __restrict__ WTf, const float* __restrict__ WTb,
              const float* __restrict__ bf, const float* __restrict__ bbp,
              float* __restrict__ hn, float* __restrict__ hb) {
    int r   = blockIdx.x & 7;
    int cid = blockIdx.x >> 3;       // 0..15
    int d   = cid >> 3;              // direction
    int pr  = cid & 7;               // batch pair
    int b0 = 2 * pr, b1 = 2 * pr + 1;
    const float* A    = d ? Ab  : Af;
    const float* WT   = d ? WTb : WTf;
    const float* bias = d ? bbp : bf;
    float* H          = d ? hb  : hn;

    __shared__ __align__(16) float hs[2][2][HH];   // [buf][bat][k]
    __shared__ float zp[2][4][128];                // [bat][quarter][localrow]

    int tid = threadIdx.x;
    int q  = tid >> 7;               // k-quarter 0..3 (uniform per warp)
    int lr = tid & 127;              // local row
    int row = (lr >> 5) * 256 + r * 32 + (lr & 31);

    unsigned long long w2[32];
    {
        const ulonglong2* wp = (const ulonglong2*)(WT + (size_t)row * 256 + q * 64);
#pragma unroll
        for (int i = 0; i < 16; i++) { ulonglong2 v = wp[i]; w2[2*i] = v.x; w2[2*i+1] = v.y; }
    }

    bool is_gate = tid < 64;
    int gb = tid >> 5, gk = tid & 31;          // (batch, k-slot) for gate threads
    int bq = gb ? b1 : b0;
    float c = 0.f;
    float bias4[4];
    if (is_gate) {
#pragma unroll
        for (int g = 0; g < 4; g++) bias4[g] = bias[g * 256 + r * 32 + gk];
    }
    if (tid < 512) hs[0][tid >> 8][tid & 255] = 0.f;
    __syncthreads();
    cluster_sync();

    int p = 0;
    for (int step = 0; step < SS; ++step) {
        int t = d ? (SS - 1 - step) : step;
        float av[4];
        if (is_gate) {
            const float* Ap = A + ((size_t)(bq * SS + t)) * G4 + r * 32 + gk;
#pragma unroll
            for (int g = 0; g < 4; g++) av[g] = Ap[g * 256];
        }
        // dot: 2 batches, register weights x smem h (broadcast LDS)
        unsigned long long a0a = 0ull, a0b = 0ull, a1a = 0ull, a1b = 0ull;
        const ulonglong2* h0 = (const ulonglong2*)&hs[p][0][q * 64];
        const ulonglong2* h1 = (const ulonglong2*)&hs[p][1][q * 64];
#pragma unroll
        for (int i = 0; i < 16; i++) {
            ulonglong2 x0 = h0[i], x1 = h1[i];
            a0a = fma2(x0.x, w2[2*i], a0a); a0b = fma2(x0.y, w2[2*i+1], a0b);
            a1a = fma2(x1.x, w2[2*i], a1a); a1b = fma2(x1.y, w2[2*i+1], a1b);
        }
        float2 u0 = unpk(fma2(splat2(1.f), a0a, a0b));
        float2 u1 = unpk(fma2(splat2(1.f), a1a, a1b));
        zp[0][q][lr] = u0.x + u0.y;
        zp[1][q][lr] = u1.x + u1.y;
        __syncthreads();

        if (is_gate) {
            float z[4];
#pragma unroll
            for (int g = 0; g < 4; g++) {
                int l = g * 32 + gk;
                z[g] = zp[gb][0][l] + zp[gb][1][l] + zp[gb][2][l] + zp[gb][3][l]
                     + av[g] + bias4[g];
            }
            float iv = sigf(z[0]), fv = sigf(z[1]);
            float gv = tanhf(z[2]), ov = sigf(z[3]);
            c = fv * c + iv * gv;
            float h = ov * tanhf(c);
            int k = r * 32 + gk;
            unsigned int base = smem_u32(&hs[1 - p][gb][k]);
#pragma unroll
            for (int cta = 0; cta < 8; cta++) st_cluster_f32(base, cta, h);
            H[((size_t)(bq * SS + t)) * HH + k] = h;
        }
        cluster_sync();
        p ^= 1;
    }
}

// ---------- decoder: 8 clusters (2 batches each) = 64 CTAs ----------
__global__ __launch_bounds__(512, 1) __cluster_dims__(8, 1, 1)
void lstm_dec(const float* __restrict__ G, const float* __restrict__ WT,
              const float* __restrict__ bias, const float* __restrict__ hn,
              const float* __restrict__ P, const float* __restrict__ b3,
              const float* __restrict__ W4, const float* __restrict__ vt1,
              float* __restrict__ out) {
    int r   = blockIdx.x & 7;
    int cid = blockIdx.x >> 3;       // 0..7
    int b0 = 2 * cid, b1 = 2 * cid + 1;

    __shared__ __align__(16) float hs[2][2][HH];
    __shared__ float zp[2][4][128];
    __shared__ __align__(16) float qp[2][WT_];
    __shared__ __align__(16) float qv[WT_];
    __shared__ __align__(16) float vs[WT_];
    __shared__ float rs[16];
    __shared__ int   ri[16];
    __shared__ int   bond_s[2];

    int tid = threadIdx.x;
    int q  = tid >> 7;
    int lr = tid & 127;
    int row = (lr >> 5) * 256 + r * 32 + (lr & 31);

    unsigned long long w2[32];
    {
        const ulonglong2* wp = (const ulonglong2*)(WT + (size_t)row * 256 + q * 64);
#pragma unroll
        for (int i = 0; i < 16; i++) { ulonglong2 v = wp[i]; w2[2*i] = v.x; w2[2*i+1] = v.y; }
    }

    bool is_gate = tid < 64;
    int gb = tid >> 5, gk = tid & 31;
    int bq = gb ? b1 : b0;
    float c = 0.f;
    float bias4[4];
    if (is_gate) {
#pragma unroll
        for (int g = 0; g < 4; g++) bias4[g] = bias[g * 256 + r * 32 + gk];
        c = hn[((size_t)(bq * SS + SS - 1)) * HH + r * 32 + gk];   // cell init = hn[-1]
    }
    if (tid < 512) hs[0][tid >> 8][tid & 255] = 0.f;
    if (tid < 256) vs[tid] = vt1[tid];
    if (tid < 2)   bond_s[tid] = 0;
    if (r == 0) {
        for (int i = tid; i < SS; i += 512) {
            out[(size_t)i * BB + b0] = 0.f;
            out[(size_t)i * BB + b1] = 0.f;
        }
    }
    __syncthreads();
    cluster_sync();

    int p = 0;
    for (int t = 0; t < SS; ++t) {
        float av[4];
        if (is_gate) {
            if (t > 0) {
                const float* Gp = G + ((size_t)(bq * SS + t - 1)) * G4 + r * 32 + gk;
#pragma unroll
                for (int g = 0; g < 4; g++) av[g] = Gp[g * 256];
            } else {
#pragma unroll
                for (int g = 0; g < 4; g++) av[g] = 0.f;
            }
        }
        unsigned long long a0a = 0ull, a0b = 0ull, a1a = 0ull, a1b = 0ull;
        const ulonglong2* h0 = (const ulonglong2*)&hs[p][0][q * 64];
        const ulonglong2* h1 = (const ulonglong2*)&hs[p][1][q * 64];
#pragma unroll
        for (int i = 0; i < 16; i++) {
            ulonglong2 x0 = h0[i], x1 = h1[i];
            a0a = fma2(x0.x, w2[2*i], a0a); a0b = fma2(x0.y, w2[2*i+1], a0b);
            a1a = fma2(x1.x, w2[2*i], a1a); a1b = fma2(x1.y, w2[2*i+1], a1b);
        }
        float2 u0 = unpk(fma2(splat2(1.f), a0a, a0b));
        float2 u1 = unpk(fma2(splat2(1.f), a1a, a1b));
        zp[0][q][lr] = u0.x + u0.y;
        zp[1][q][lr] = u1.x + u1.y;
        __syncthreads();

        if (is_gate) {
            float z[4];
#pragma unroll
            for (int g = 0; g < 4; g++) {
                int l = g * 32 + gk;
                z[g] = zp[gb][0][l] + zp[gb][1][l] + zp[gb][2][l] + zp[gb][3][l]
                     + av[g] + bias4[g];
            }
            float iv = sigf(z[0]), fv = sigf(z[1]);
            float gv = tanhf(z[2]), ov = sigf(z[3]);
            c = fv * c + iv * gv;
            float h = ov * tanhf(c);
            int k = r * 32 + gk;
            unsigned int base = smem_u32(&hs[1 - p][gb][k]);
#pragma unroll
            for (int cta = 0; cta < 8; cta++) st_cluster_f32(base, cta, h);
        }
        cluster_sync();      // hs[1-p] now complete in every CTA
        p ^= 1;

        // ---- decision steps: replicated identically in all 8 CTAs ----
#pragma unroll 1
        for (int bat = 0; bat < 2; ++bat) {
            if (t != bond_s[bat]) continue;
            int b = bat ? b1 : b0;
            // qv = b3[b][t] + h @ W4   (h = hs[p][bat], the new hidden)
            {
                int j = tid & 255, kh = tid >> 8;
                const float* w4p = W4 + (size_t)(kh * 128) * WT_ + j;
                const float* hh = &hs[p][bat][kh * 128];
                float acc = 0.f;
#pragma unroll 4
                for (int k = 0; k < 128; ++k) acc += hh[k] * w4p[(size_t)k * WT_];
                qp[kh][j] = acc;
            }
            __syncthreads();
            if (tid < 256)
                qv[tid] = qp[0][tid] + qp[1][tid] + b3[((size_t)(b * SS + t)) * WT_ + tid];
            __syncthreads();
            // warp-per-position, lane-coalesced score
            int wp = tid >> 5, lane = tid & 31;
            float best = -3.4e38f; int bi = 0x7fffffff;
            for (int pos = t + wp; pos < SS; pos += 16) {
                const float* Pr = P + ((size_t)(b * SS + pos)) * WT_;
                float4 p0 = *(const float4*)(Pr + lane * 4);
                float4 p1 = *(const float4*)(Pr + 128 + lane * 4);
                const float4 q0 = *(const float4*)(qv + lane * 4);
                const float4 q1 = *(const float4*)(qv + 128 + lane * 4);
                const float4 v0 = *(const float4*)(vs + lane * 4);
                const float4 v1 = *(const float4*)(vs + 128 + lane * 4);
                float s = v0.x * tanhf(p0.x + q0.x) + v0.y * tanhf(p0.y + q0.y)
                        + v0.z * tanhf(p0.z + q0.z) + v0.w * tanhf(p0.w + q0.w)
                        + v1.x * tanhf(p1.x + q1.x) + v1.y * tanhf(p1.y + q1.y)
                        + v1.z * tanhf(p1.z + q1.z) + v1.w * tanhf(p1.w + q1.w);
#pragma unroll
                for (int off = 16; off > 0; off >>= 1)
                    s += __shfl_down_sync(0xffffffffu, s, off);
                s = __shfl_sync(0xffffffffu, s, 0);
                if (s > best) { best = s; bi = pos; }   // increasing pos: ties keep first
            }
            if (lane == 0) { rs[wp] = best; ri[wp] = bi; }
            __syncthreads();
            if (tid == 0) {
                float bb = rs[0]; int bx = ri[0];
#pragma unroll
                for (int w = 1; w < 16; w++)
                    if (rs[w] > bb || (rs[w] == bb && ri[w] < bx)) { bb = rs[w]; bx = ri[w]; }
                bond_s[bat] = bx;
                if (r == 0) out[(size_t)bx * BB + b] = 1.0f;
            }
            __syncthreads();
        }
    }
}

extern "C" void kernel_launch(void* const* d_in, const int* in_sizes, int n_in,
                              void* d_out, int out_size) {
    const float* x        = (const float*)d_in[0];
    const float* eWih_f   = (const float*)d_in[1];
    const float* eWhh_f   = (const float*)d_in[2];
    const float* eb_f     = (const float*)d_in[3];
    const float* eWih_b   = (const float*)d_in[4];
    const float* eWhh_b   = (const float*)d_in[5];
    const float* eb_b     = (const float*)d_in[6];
    const float* dWih     = (const float*)d_in[7];
    const float* dWhh     = (const float*)d_in[8];
    const float* db       = (const float*)d_in[9];
    const float* W1       = (const float*)d_in[10];
    const float* W2       = (const float*)d_in[11];
    const float* W3       = (const float*)d_in[12];
    const float* W4       = (const float*)d_in[13];
    const float* vt1      = (const float*)d_in[14];
    float* out = (float*)d_out;

    float *Af, *Ab, *G, *hn, *hb, *P, *b3, *WTf, *WTb, *WTd;
    cudaGetSymbolAddress((void**)&Af,  g_Af);
    cudaGetSymbolAddress((void**)&Ab,  g_Ab);
    cudaGetSymbolAddress((void**)&G,   g_G);
    cudaGetSymbolAddress((void**)&hn,  g_hn);
    cudaGetSymbolAddress((void**)&hb,  g_hb);
    cudaGetSymbolAddress((void**)&P,   g_P);
    cudaGetSymbolAddress((void**)&b3,  g_b3);
    cudaGetSymbolAddress((void**)&WTf, g_WTf);
    cudaGetSymbolAddress((void**)&WTb, g_WTb);
    cudaGetSymbolAddress((void**)&WTd, g_WTd);

    dim3 tb(32, 32), tg(G4 / 32, HH / 32);
    transpose_w<<<tg, tb>>>(eWhh_f, WTf);
    transpose_w<<<tg, tb>>>(eWhh_b, WTb);
    transpose_w<<<tg, tb>>>(dWhh,   WTd);

    const int M = BB * SS;
    sgemm128<<<dim3(G4 / 128, M / 128), 256>>>(x, eWih_f, Af, M, G4, EE, 0);
    sgemm128<<<dim3(G4 / 128, M / 128), 256>>>(x, eWih_b, Ab, M, G4, EE, 0);

    lstm_enc<<<128, 512>>>(Af, Ab, WTf, WTb, eb_f, eb_b, hn, hb);

    sgemm128<<<dim3(G4 / 128, M / 128), 256>>>(x,  dWih,           G, M, G4, EE, 0);
    sgemm128<<<dim3(G4 / 128, M / 128), 256>>>(hn, dWih + EE * G4, G, M, G4, HH, 1);

    sgemm128<<<dim3(WT_ / 128, M / 128), 256>>>(hn, W1,            P,  M, WT_, HH, 0);
    sgemm128<<<dim3(WT_ / 128, M / 128), 256>>>(hb, W1 + HH * WT_, P,  M, WT_, HH, 1);
    sgemm128<<<dim3(WT_ / 128, M / 128), 256>>>(x,  W2,            P,  M, WT_, EE, 1);
    sgemm128<<<dim3(WT_ / 128, M / 128), 256>>>(x,  W3,            b3, M, WT_, EE, 0);

    lstm_dec<<<64, 512>>>(G, WTd, db, hn, P, b3, W4, vt1, out);
}